// round 16
// baseline (speedup 1.0000x reference)
#include <cuda_runtime.h>
#include <cuda_bf16.h>
#include <mma.h>

using namespace nvcuda;

#define NB   4096
#define NB2  8192
#define NT   30

// ---------------- static device scratch (no allocations allowed) ----------------
__device__ float g_Xc [(size_t)NB2*NT*64];     // packed/padded input  [8192*30][64]
__device__ float g_XG1[(size_t)NB2*NT*2048];   // layer1 input preacts (gate-interleaved)
__device__ float g_H1S[(size_t)NB2*NT*512];    // relu(h1) sequence
__device__ float g_XG2[(size_t)NB2*NT*512];
__device__ float g_H2S[(size_t)NB2*NT*128];
__device__ float g_XG3[(size_t)NB2*NT*256];
__device__ float g_H3S[(size_t)NB2*NT*64];
__device__ float g_Ha [NB2*512];
__device__ float g_Hb [NB2*512];
__device__ float g_Cc [NB2*512];
__device__ float g_D  [(size_t)NB*1920];
__device__ float g_F1 [NB*960];
__device__ float g_F2 [NB*480];
// gate-interleaved (+padded) weight copies
__device__ float g_Wih1p[2048*64];
__device__ float g_Whh1p[2048*512];
__device__ float g_b1p  [2048];
__device__ float g_Wih2p[512*512];
__device__ float g_Whh2p[512*128];
__device__ float g_b2p  [512];
__device__ float g_Wih3p[256*128];
__device__ float g_Whh3p[256*64];
__device__ float g_b3p  [256];

// ---------------- device helpers ----------------
__device__ __forceinline__ float sigmf(float x) {
    return __fdividef(1.f, 1.f + __expf(-x));
}
__device__ __forceinline__ float tanh_f(float x) {
    float xc = fminf(fmaxf(x, -15.f), 15.f);
    float e  = __expf(2.f * xc);
    return __fdividef(e - 1.f, e + 1.f);
}

// ---------------- small prep kernels ----------------
__global__ void pack_x(const float* __restrict__ x1, const float* __restrict__ x2,
                       float* __restrict__ Xc) {
    size_t i = (size_t)blockIdx.x * blockDim.x + threadIdx.x;
    if (i >= (size_t)NB2 * NT * 64) return;
    int    f  = (int)(i & 63);
    size_t bt = i >> 6;
    int    t  = (int)(bt % NT);
    size_t bb = bt / NT;
    int    br = (int)(bb >> 12);
    int    b  = (int)(bb & 4095);
    const float* x = br ? x2 : x1;
    Xc[i] = (f < 58) ? x[(size_t)b * (58 * 30) + f * 30 + t] : 0.f;
}

__global__ void perm_wih1(const float* __restrict__ W, float* __restrict__ Wp) {
    int i = blockIdx.x * blockDim.x + threadIdx.x;
    if (i >= 2048 * 64) return;
    int f = i & 63, p = i >> 6;
    int u = p >> 2, g = p & 3;
    Wp[i] = (f < 58) ? W[(g * 512 + u) * 58 + f] : 0.f;
}

// out row p=4u+g <- in row g*H+u, row length K
__global__ void perm_w(const float* __restrict__ W, float* __restrict__ Wp, int H, int K) {
    int i = blockIdx.x * blockDim.x + threadIdx.x;
    if (i >= 4 * H * K) return;
    int k = i % K, p = i / K;
    int u = p >> 2, g = p & 3;
    Wp[i] = W[(size_t)(g * H + u) * K + k];
}

__global__ void perm_b(const float* __restrict__ b, float* __restrict__ bp, int H) {
    int i = blockIdx.x * blockDim.x + threadIdx.x;
    if (i >= 4 * H) return;
    int u = i >> 2, g = i & 3;
    bp[i] = b[g * H + u];
}

// ---------------- generic bf16x3 GEMM: C[M,N] = A[M,K] * W[N,K]^T (+bias)(+relu) ----------------
// M multiple of 64, K multiple of 32. N arbitrary (bounds-checked).
__global__ __launch_bounds__(128) void gemm_bf16x3(
    const float* __restrict__ A, const float* __restrict__ W,
    const float* __restrict__ bias, float* __restrict__ Co,
    int M, int N, int K, int relu)
{
    __shared__ __align__(16) unsigned char sbuf[20608];
    __nv_bfloat16* Ah = (__nv_bfloat16*)sbuf;
    __nv_bfloat16* Al = Ah + 2560;
    __nv_bfloat16* Bh = Ah + 5120;
    __nv_bfloat16* Bl = Ah + 7680;
    float* Cs = (float*)sbuf;

    const int row0 = blockIdx.y * 64;
    const int col0 = blockIdx.x * 64;
    const int tid  = threadIdx.x;
    const int warp = tid >> 5;
    const int wm = (warp >> 1) * 32, wn = (warp & 1) * 32;

    wmma::fragment<wmma::accumulator, 16, 16, 16, float> acc[2][2];
#pragma unroll
    for (int i = 0; i < 2; i++)
#pragma unroll
        for (int j = 0; j < 2; j++) wmma::fill_fragment(acc[i][j], 0.f);

    for (int k0 = 0; k0 < K; k0 += 32) {
        __syncthreads();
#pragma unroll
        for (int it = 0; it < 4; it++) {
            int idx = tid + it * 128;
            int r = idx >> 3;
            int c = (idx & 7) << 2;
            float4 va = *(const float4*)(A + (size_t)(row0 + r) * K + k0 + c);
            int n = col0 + r;
            float4 vb = make_float4(0.f, 0.f, 0.f, 0.f);
            if (n < N) vb = *(const float4*)(W + (size_t)n * K + k0 + c);
            float fa[4] = {va.x, va.y, va.z, va.w};
            float fb[4] = {vb.x, vb.y, vb.z, vb.w};
#pragma unroll
            for (int q = 0; q < 4; q++) {
                __nv_bfloat16 h1 = __float2bfloat16(fa[q]);
                Ah[r * 40 + c + q] = h1;
                Al[r * 40 + c + q] = __float2bfloat16(fa[q] - __bfloat162float(h1));
                __nv_bfloat16 h2 = __float2bfloat16(fb[q]);
                Bh[r * 40 + c + q] = h2;
                Bl[r * 40 + c + q] = __float2bfloat16(fb[q] - __bfloat162float(h2));
            }
        }
        __syncthreads();
#pragma unroll
        for (int kk = 0; kk < 32; kk += 16) {
            wmma::fragment<wmma::matrix_a, 16, 16, 16, __nv_bfloat16, wmma::row_major> ah[2], al[2];
            wmma::fragment<wmma::matrix_b, 16, 16, 16, __nv_bfloat16, wmma::col_major> bh[2], bl[2];
#pragma unroll
            for (int i = 0; i < 2; i++) {
                wmma::load_matrix_sync(ah[i], Ah + (wm + i * 16) * 40 + kk, 40);
                wmma::load_matrix_sync(al[i], Al + (wm + i * 16) * 40 + kk, 40);
                wmma::load_matrix_sync(bh[i], Bh + (wn + i * 16) * 40 + kk, 40);
                wmma::load_matrix_sync(bl[i], Bl + (wn + i * 16) * 40 + kk, 40);
            }
#pragma unroll
            for (int i = 0; i < 2; i++)
#pragma unroll
                for (int j = 0; j < 2; j++) {
                    wmma::mma_sync(acc[i][j], ah[i], bh[j], acc[i][j]);
                    wmma::mma_sync(acc[i][j], ah[i], bl[j], acc[i][j]);
                    wmma::mma_sync(acc[i][j], al[i], bh[j], acc[i][j]);
                }
        }
    }
    __syncthreads();
#pragma unroll
    for (int i = 0; i < 2; i++)
#pragma unroll
        for (int j = 0; j < 2; j++)
            wmma::store_matrix_sync(Cs + (wm + i * 16) * 68 + wn + j * 16, acc[i][j], 68,
                                    wmma::mem_row_major);
    __syncthreads();

    for (int idx = tid; idx < 64 * 64; idx += 128) {
        int r = idx >> 6, c = idx & 63;
        int n = col0 + c;
        if (n < N) {
            float v = Cs[r * 68 + c];
            if (bias) v += bias[n];
            if (relu) v = fmaxf(v, 0.f);
            Co[(size_t)(row0 + r) * N + n] = v;
        }
    }
}

// ---------------- fused recurrent step: G = Hin*Whh^T + XG[t]; LSTM cell epilogue ----------------
// Weights/XG gate-interleaved: column 4*u+g. N=4H, K=H (multiples of 64/32 for all layers).
__global__ __launch_bounds__(128) void lstm_step(
    const float* __restrict__ A, const float* __restrict__ W,
    const float* __restrict__ XG, float* __restrict__ C,
    float* __restrict__ Hn, float* __restrict__ SEQ,
    int H, int t)
{
    const int K = H, N = 4 * H;
    __shared__ __align__(16) unsigned char sbuf[20608];
    __nv_bfloat16* Ah = (__nv_bfloat16*)sbuf;
    __nv_bfloat16* Al = Ah + 2560;
    __nv_bfloat16* Bh = Ah + 5120;
    __nv_bfloat16* Bl = Ah + 7680;
    float* Cs = (float*)sbuf;

    const int row0 = blockIdx.y * 64;
    const int col0 = blockIdx.x * 64;
    const int tid  = threadIdx.x;
    const int warp = tid >> 5;
    const int wm = (warp >> 1) * 32, wn = (warp & 1) * 32;

    wmma::fragment<wmma::accumulator, 16, 16, 16, float> acc[2][2];
#pragma unroll
    for (int i = 0; i < 2; i++)
#pragma unroll
        for (int j = 0; j < 2; j++) wmma::fill_fragment(acc[i][j], 0.f);

    for (int k0 = 0; k0 < K; k0 += 32) {
        __syncthreads();
#pragma unroll
        for (int it = 0; it < 4; it++) {
            int idx = tid + it * 128;
            int r = idx >> 3;
            int c = (idx & 7) << 2;
            float4 va = *(const float4*)(A + (size_t)(row0 + r) * K + k0 + c);
            float4 vb = *(const float4*)(W + (size_t)(col0 + r) * K + k0 + c);
            float fa[4] = {va.x, va.y, va.z, va.w};
            float fb[4] = {vb.x, vb.y, vb.z, vb.w};
#pragma unroll
            for (int q = 0; q < 4; q++) {
                __nv_bfloat16 h1 = __float2bfloat16(fa[q]);
                Ah[r * 40 + c + q] = h1;
                Al[r * 40 + c + q] = __float2bfloat16(fa[q] - __bfloat162float(h1));
                __nv_bfloat16 h2 = __float2bfloat16(fb[q]);
                Bh[r * 40 + c + q] = h2;
                Bl[r * 40 + c + q] = __float2bfloat16(fb[q] - __bfloat162float(h2));
            }
        }
        __syncthreads();
#pragma unroll
        for (int kk = 0; kk < 32; kk += 16) {
            wmma::fragment<wmma::matrix_a, 16, 16, 16, __nv_bfloat16, wmma::row_major> ah[2], al[2];
            wmma::fragment<wmma::matrix_b, 16, 16, 16, __nv_bfloat16, wmma::col_major> bh[2], bl[2];
#pragma unroll
            for (int i = 0; i < 2; i++) {
                wmma::load_matrix_sync(ah[i], Ah + (wm + i * 16) * 40 + kk, 40);
                wmma::load_matrix_sync(al[i], Al + (wm + i * 16) * 40 + kk, 40);
                wmma::load_matrix_sync(bh[i], Bh + (wn + i * 16) * 40 + kk, 40);
                wmma::load_matrix_sync(bl[i], Bl + (wn + i * 16) * 40 + kk, 40);
            }
#pragma unroll
            for (int i = 0; i < 2; i++)
#pragma unroll
                for (int j = 0; j < 2; j++) {
                    wmma::mma_sync(acc[i][j], ah[i], bh[j], acc[i][j]);
                    wmma::mma_sync(acc[i][j], ah[i], bl[j], acc[i][j]);
                    wmma::mma_sync(acc[i][j], al[i], bh[j], acc[i][j]);
                }
        }
    }
    __syncthreads();
#pragma unroll
    for (int i = 0; i < 2; i++)
#pragma unroll
        for (int j = 0; j < 2; j++)
            wmma::store_matrix_sync(Cs + (wm + i * 16) * 68 + wn + j * 16, acc[i][j], 68,
                                    wmma::mem_row_major);
    __syncthreads();

    // LSTM cell epilogue: each (row, unit) has its 4 gates in 4 consecutive cols (i,f,g,o)
    const int ucol0 = col0 >> 2;
    for (int idx = tid; idx < 64 * 16; idx += 128) {
        int r  = idx >> 4, ul = idx & 15;
        int b  = row0 + r;
        int ug = ucol0 + ul;
        const float4 xg = *(const float4*)(XG + ((size_t)b * NT + t) * N + 4 * ug);
        float ip = Cs[r * 68 + ul * 4 + 0] + xg.x;
        float fp = Cs[r * 68 + ul * 4 + 1] + xg.y;
        float gp = Cs[r * 68 + ul * 4 + 2] + xg.z;
        float op = Cs[r * 68 + ul * 4 + 3] + xg.w;
        size_t ci = (size_t)b * H + ug;
        float c = sigmf(fp) * C[ci] + sigmf(ip) * tanh_f(gp);
        float h = sigmf(op) * tanh_f(c);
        C[ci]  = c;
        Hn[ci] = h;
        SEQ[((size_t)b * NT + t) * H + ug] = fmaxf(h, 0.f);
    }
}

// t=0 cell (h0=c0=0, no recurrent GEMM)
__global__ void gate_init(const float* __restrict__ XG, float* __restrict__ C,
                          float* __restrict__ Hc, float* __restrict__ SEQ, int H) {
    int i = blockIdx.x * blockDim.x + threadIdx.x;
    if (i >= NB2 * H) return;
    int b = i / H, u = i - b * H;
    const float4 xg = *(const float4*)(XG + (size_t)b * NT * (4 * H) + 4 * u);
    float c = sigmf(xg.x) * tanh_f(xg.z);
    float h = sigmf(xg.w) * tanh_f(c);
    C[i]  = c;
    Hc[i] = h;
    SEQ[(size_t)b * NT * H + u] = fmaxf(h, 0.f);
}

__global__ void absdiff(const float* __restrict__ H3, float* __restrict__ D) {
    size_t i = (size_t)blockIdx.x * blockDim.x + threadIdx.x;
    if (i >= (size_t)NB * 1920) return;
    D[i] = fabsf(H3[i] - H3[i + (size_t)NB * 1920]);
}

// fused FC3(480->16, relu) + FC4(16->1)
__global__ void fc34(const float* __restrict__ F2, const float* __restrict__ Wf3,
                     const float* __restrict__ bf3, const float* __restrict__ Wf4,
                     const float* __restrict__ bf4, float* __restrict__ out) {
    __shared__ float row[480];
    __shared__ float acc16[16];
    int b = blockIdx.x, tid = threadIdx.x;
    for (int i = tid; i < 480; i += 256) row[i] = F2[(size_t)b * 480 + i];
    __syncthreads();
    int n = tid >> 4, lane = tid & 15;
    float s = 0.f;
    for (int k = lane; k < 480; k += 16) s += row[k] * Wf3[n * 480 + k];
#pragma unroll
    for (int off = 8; off; off >>= 1) s += __shfl_down_sync(0xffffffffu, s, off, 16);
    if (lane == 0) acc16[n] = fmaxf(s + bf3[n], 0.f) * Wf4[n];
    __syncthreads();
    if (tid == 0) {
        float r = bf4[0];
#pragma unroll
        for (int i = 0; i < 16; i++) r += acc16[i];
        out[b] = r;
    }
}

// ---------------- host orchestration ----------------
extern "C" void kernel_launch(void* const* d_in, const int* in_sizes, int n_in,
                              void* d_out, int out_size) {
    (void)in_sizes; (void)out_size;
    if (n_in < 19) return;
    const float* x1   = (const float*)d_in[0];
    const float* x2   = (const float*)d_in[1];
    const float* Wih1 = (const float*)d_in[2];
    const float* Whh1 = (const float*)d_in[3];
    const float* b1   = (const float*)d_in[4];
    const float* Wih2 = (const float*)d_in[5];
    const float* Whh2 = (const float*)d_in[6];
    const float* b2   = (const float*)d_in[7];
    const float* Wih3 = (const float*)d_in[8];
    const float* Whh3 = (const float*)d_in[9];
    const float* b3   = (const float*)d_in[10];
    const float* Wf1  = (const float*)d_in[11];
    const float* bf1  = (const float*)d_in[12];
    const float* Wf2  = (const float*)d_in[13];
    const float* bf2  = (const float*)d_in[14];
    const float* Wf3  = (const float*)d_in[15];
    const float* bf3  = (const float*)d_in[16];
    const float* Wf4  = (const float*)d_in[17];
    const float* bf4  = (const float*)d_in[18];

    float *Xc, *XG1, *H1S, *XG2, *H2S, *XG3, *H3S, *Ha, *Hb, *Cc, *D, *F1, *F2;
    float *Wih1p, *Whh1p, *b1p, *Wih2p, *Whh2p, *b2p, *Wih3p, *Whh3p, *b3p;
    cudaGetSymbolAddress((void**)&Xc,  g_Xc);
    cudaGetSymbolAddress((void**)&XG1, g_XG1);
    cudaGetSymbolAddress((void**)&H1S, g_H1S);
    cudaGetSymbolAddress((void**)&XG2, g_XG2);
    cudaGetSymbolAddress((void**)&H2S, g_H2S);
    cudaGetSymbolAddress((void**)&XG3, g_XG3);
    cudaGetSymbolAddress((void**)&H3S, g_H3S);
    cudaGetSymbolAddress((void**)&Ha,  g_Ha);
    cudaGetSymbolAddress((void**)&Hb,  g_Hb);
    cudaGetSymbolAddress((void**)&Cc,  g_Cc);
    cudaGetSymbolAddress((void**)&D,   g_D);
    cudaGetSymbolAddress((void**)&F1,  g_F1);
    cudaGetSymbolAddress((void**)&F2,  g_F2);
    cudaGetSymbolAddress((void**)&Wih1p, g_Wih1p);
    cudaGetSymbolAddress((void**)&Whh1p, g_Whh1p);
    cudaGetSymbolAddress((void**)&b1p,   g_b1p);
    cudaGetSymbolAddress((void**)&Wih2p, g_Wih2p);
    cudaGetSymbolAddress((void**)&Whh2p, g_Whh2p);
    cudaGetSymbolAddress((void**)&b2p,   g_b2p);
    cudaGetSymbolAddress((void**)&Wih3p, g_Wih3p);
    cudaGetSymbolAddress((void**)&Whh3p, g_Whh3p);
    cudaGetSymbolAddress((void**)&b3p,   g_b3p);

    // prep
    pack_x<<<61440, 256>>>(x1, x2, Xc);
    perm_wih1<<<512, 256>>>(Wih1, Wih1p);
    perm_w<<<4096, 256>>>(Whh1, Whh1p, 512, 512);
    perm_b<<<8, 256>>>(b1, b1p, 512);
    perm_w<<<1024, 256>>>(Wih2, Wih2p, 128, 512);
    perm_w<<<256, 256>>>(Whh2, Whh2p, 128, 128);
    perm_b<<<2, 256>>>(b2, b2p, 128);
    perm_w<<<128, 256>>>(Wih3, Wih3p, 64, 128);
    perm_w<<<64, 256>>>(Whh3, Whh3p, 64, 64);
    perm_b<<<1, 256>>>(b3, b3p, 64);

    const int MBT = NB2 * NT;  // 245760

    // ---- layer 1: 58(->64) -> 512 ----
    gemm_bf16x3<<<dim3(32, MBT / 64), 128>>>(Xc, Wih1p, b1p, XG1, MBT, 2048, 64, 0);
    gate_init<<<(NB2 * 512) / 256, 256>>>(XG1, Cc, Ha, H1S, 512);
    for (int t = 1; t < NT; t++) {
        float* Ain  = (t & 1) ? Ha : Hb;
        float* Aout = (t & 1) ? Hb : Ha;
        lstm_step<<<dim3(32, NB2 / 64), 128>>>(Ain, Whh1p, XG1, Cc, Aout, H1S, 512, t);
    }

    // ---- layer 2: 512 -> 128 ----
    gemm_bf16x3<<<dim3(8, MBT / 64), 128>>>(H1S, Wih2p, b2p, XG2, MBT, 512, 512, 0);
    gate_init<<<(NB2 * 128) / 256, 256>>>(XG2, Cc, Ha, H2S, 128);
    for (int t = 1; t < NT; t++) {
        float* Ain  = (t & 1) ? Ha : Hb;
        float* Aout = (t & 1) ? Hb : Ha;
        lstm_step<<<dim3(8, NB2 / 64), 128>>>(Ain, Whh2p, XG2, Cc, Aout, H2S, 128, t);
    }

    // ---- layer 3: 128 -> 64 ----
    gemm_bf16x3<<<dim3(4, MBT / 64), 128>>>(H2S, Wih3p, b3p, XG3, MBT, 256, 128, 0);
    gate_init<<<(NB2 * 64) / 256, 256>>>(XG3, Cc, Ha, H3S, 64);
    for (int t = 1; t < NT; t++) {
        float* Ain  = (t & 1) ? Ha : Hb;
        float* Aout = (t & 1) ? Hb : Ha;
        lstm_step<<<dim3(4, NB2 / 64), 128>>>(Ain, Whh3p, XG3, Cc, Aout, H3S, 64, t);
    }

    // ---- siamese diff + FC head ----
    absdiff<<<(NB * 1920) / 256, 256>>>(H3S, D);
    gemm_bf16x3<<<dim3(15, NB / 64), 128>>>(D, Wf1, bf1, F1, NB, 960, 1920, 1);
    gemm_bf16x3<<<dim3(8, NB / 64), 128>>>(F1, Wf2, bf2, F2, NB, 480, 960, 1);
    fc34<<<NB, 256>>>(F2, Wf3, bf3, Wf4, bf4, (float*)d_out);
}